// round 16
// baseline (speedup 1.0000x reference)
#include <cuda_runtime.h>
#include <cuda_bf16.h>
#include <cuda_fp16.h>
#include <cstdint>

#define BATCH   32
#define CHN     256
#define HW      1024
#define P_TOTAL 32768
#define NE      1024
#define LOSS_OFF    8388608
#define IDX_OFF     8388609
#define MARGIN  4e-3f
#define THETA   1e-3f

__device__ float  g_zT[P_TOTAL * CHN];
__device__ float  g_ze[P_TOTAL * CHN];           // approx embedded
__device__ float  g_wTe[9 * CHN * CHN];          // [t][i][o] fp32 (exact fixup)
__device__ float  g_wTu[9 * CHN * CHN];
__device__ __nv_bfloat16 g_whi[9 * CHN * CHN];   // [t][o][i] bf16
__device__ float  g_U[NE * 9 * CHN];
__device__ float  g_cn[NE];
__device__ float  g_zn[P_TOTAL];
__device__ __half g_S[(size_t)P_TOTAL * NE];
__device__ int    g_idx[P_TOTAL];
__device__ int    g_risky[P_TOTAL];
__device__ int    g_nrisky;
__device__ float  g_partial[4096];

__device__ __forceinline__ uint32_t smem_u32(const void* p) {
    uint32_t a;
    asm("{ .reg .u64 t; cvta.to.shared.u64 t, %1; cvt.u32.u64 %0, t; }"
        : "=r"(a) : "l"(p));
    return a;
}

__global__ void k_transpose(const float* __restrict__ z)
{
    __shared__ float t[32][33];
    int b = blockIdx.z, c0 = blockIdx.y * 32, hw0 = blockIdx.x * 32;
    int tx = threadIdx.x, ty = threadIdx.y;
#pragma unroll
    for (int r = 0; r < 32; r += 8)
        t[ty + r][tx] = z[((size_t)(b * CHN + c0 + ty + r)) * HW + hw0 + tx];
    __syncthreads();
#pragma unroll
    for (int r = 0; r < 32; r += 8)
        g_zT[((size_t)(b * HW + hw0 + ty + r)) * CHN + c0 + tx] = t[tx][ty + r];
}

__global__ void k_reorgW(const float* __restrict__ w, int which)
{
    int idx = blockIdx.x * 256 + threadIdx.x;
    if (idx >= 9 * CHN * CHN) return;
    int t = idx % 9, i = (idx / 9) % CHN, o = idx / (9 * CHN);
    float v = w[idx];
    if (which) { g_wTu[(t * CHN + i) * CHN + o] = v; return; }
    g_wTe[(t * CHN + i) * CHN + o] = v;
    g_whi[(t * CHN + o) * CHN + i] = __float2bfloat16(v);
}

__device__ __forceinline__ float row_sumsq_seq(const float* __restrict__ row)
{
    float acc = 0.f;
#pragma unroll 8
    for (int c = 0; c < CHN; ++c)
        acc = __fadd_rn(acc, __fmul_rn(row[c], row[c]));
    return acc;
}

__global__ void k_code_norms(const float* __restrict__ cb)
{
    if (blockIdx.x == 0 && threadIdx.x == 0) g_nrisky = 0;
    int code = blockIdx.x * 128 + threadIdx.x;
    if (code >= NE) return;
    g_cn[code] = row_sumsq_seq(cb + (size_t)code * CHN);
}

__global__ void k_row_norms()
{
    int p = blockIdx.x * 128 + threadIdx.x;
    if (p >= P_TOTAL) return;
    g_zn[p] = row_sumsq_seq(g_ze + (size_t)p * CHN);
}

// ---- approx embed conv: single-term bf16 mma.sync, pass1-shaped tile --------
// CTA 128px x 128och, K = 9 taps x 2 chunks of 128. occ 2, ~100 regs.
#define CM_STRIDE 272
#define CM_B      (128 * CM_STRIDE)
#define CM_TOTAL  (2 * 128 * CM_STRIDE)

__global__ __launch_bounds__(256, 2) void k_conv_bf16(const float* __restrict__ bias)
{
    extern __shared__ char sm[];
    __shared__ int srcRow[128];
    uint32_t smb = smem_u32(sm);

    int tid = threadIdx.x;
    int lane = tid & 31, wid = tid >> 5;
    int warp_m = wid >> 2, warp_n = wid & 3;
    int p0 = blockIdx.x * 128, o0 = blockIdx.y * 128;

    float d[4][4][4];
#pragma unroll
    for (int mt = 0; mt < 4; ++mt)
#pragma unroll
        for (int nt = 0; nt < 4; ++nt)
#pragma unroll
            for (int r = 0; r < 4; ++r) d[mt][nt][r] = 0.f;

    uint32_t a_base = smb + (uint32_t)(warp_m * 64 + (lane & 15)) * CM_STRIDE
                    + (uint32_t)(lane >> 4) * 16;
    uint32_t b_base = smb + CM_B + (uint32_t)(warp_n * 32 + (lane & 7)) * CM_STRIDE
                    + (uint32_t)((lane >> 3) & 1) * 16;

#pragma unroll 1
    for (int t = 0; t < 9; ++t) {
        int dy = t / 3 - 1, dx = t - (t / 3) * 3 - 1;
        if (tid < 128) {
            int p = p0 + tid;
            int y = (p >> 5) & 31, x = p & 31;
            int yy = y + dy, xx = x + dx;
            srcRow[tid] = ((unsigned)yy < 32u && (unsigned)xx < 32u)
                              ? (p + dy * 32 + dx) : -1;
        }
#pragma unroll 1
        for (int kk = 0; kk < 2; ++kk) {
            __syncthreads();
            // stage A: 128 px x 128 c, fp32 -> bf16 inline
#pragma unroll
            for (int l = 0; l < 8; ++l) {
                int it = tid + l * 256;       // 0..2047
                int row = it >> 4, kg = it & 15;
                int src = srcRow[row];
                uint4 pack = make_uint4(0, 0, 0, 0);
                if (src >= 0) {
                    const float4* s4 = (const float4*)(g_zT + (size_t)src * CHN
                                                       + kk * 128 + kg * 8);
                    float4 v0 = s4[0], v1 = s4[1];
                    __nv_bfloat162 b0 = __floats2bfloat162_rn(v0.x, v0.y);
                    __nv_bfloat162 b1 = __floats2bfloat162_rn(v0.z, v0.w);
                    __nv_bfloat162 b2 = __floats2bfloat162_rn(v1.x, v1.y);
                    __nv_bfloat162 b3 = __floats2bfloat162_rn(v1.z, v1.w);
                    pack = make_uint4(*(uint32_t*)&b0, *(uint32_t*)&b1,
                                      *(uint32_t*)&b2, *(uint32_t*)&b3);
                }
                *(uint4*)(sm + row * CM_STRIDE + kg * 16) = pack;
            }
            // stage B: 128 o x 128 c, bf16 direct copy
#pragma unroll
            for (int l = 0; l < 8; ++l) {
                int it = tid + l * 256;
                int row = it >> 4, kg = it & 15;
                *(uint4*)(sm + CM_B + row * CM_STRIDE + kg * 16) =
                    *(const uint4*)(g_whi + ((size_t)(t * CHN) + o0 + row) * CHN
                                    + kk * 128 + kg * 8);
            }
            __syncthreads();
#pragma unroll
            for (int ks = 0; ks < 8; ++ks) {
                uint32_t a[4][4], b[4][2];
#pragma unroll
                for (int mt = 0; mt < 4; ++mt) {
                    uint32_t addr = a_base + (uint32_t)(mt * 16) * CM_STRIDE + ks * 32;
                    asm volatile("ldmatrix.sync.aligned.m8n8.x4.shared.b16 {%0,%1,%2,%3}, [%4];"
                        : "=r"(a[mt][0]), "=r"(a[mt][1]), "=r"(a[mt][2]), "=r"(a[mt][3])
                        : "r"(addr));
                }
#pragma unroll
                for (int nt = 0; nt < 4; ++nt) {
                    uint32_t addr = b_base + (uint32_t)(nt * 8) * CM_STRIDE + ks * 32;
                    asm volatile("ldmatrix.sync.aligned.m8n8.x2.shared.b16 {%0,%1}, [%2];"
                        : "=r"(b[nt][0]), "=r"(b[nt][1]) : "r"(addr));
                }
#pragma unroll
                for (int mt = 0; mt < 4; ++mt)
#pragma unroll
                    for (int nt = 0; nt < 4; ++nt)
                        asm volatile("mma.sync.aligned.m16n8k16.row.col.f32.bf16.bf16.f32 "
                            "{%0,%1,%2,%3}, {%4,%5,%6,%7}, {%8,%9}, {%0,%1,%2,%3};"
                            : "+f"(d[mt][nt][0]), "+f"(d[mt][nt][1]),
                              "+f"(d[mt][nt][2]), "+f"(d[mt][nt][3])
                            : "r"(a[mt][0]), "r"(a[mt][1]), "r"(a[mt][2]), "r"(a[mt][3]),
                              "r"(b[nt][0]), "r"(b[nt][1]));
            }
        }
    }

    int r = lane >> 2, cp = (lane & 3) * 2;
#pragma unroll
    for (int mt = 0; mt < 4; ++mt)
#pragma unroll
        for (int nt = 0; nt < 4; ++nt) {
            int col = o0 + warp_n * 32 + nt * 8 + cp;
            float b0 = bias[col], b1 = bias[col + 1];
            int px0 = p0 + warp_m * 64 + mt * 16 + r;
            *(float2*)(g_ze + (size_t)px0 * CHN + col) =
                make_float2(d[mt][nt][0] + b0, d[mt][nt][1] + b1);
            *(float2*)(g_ze + (size_t)(px0 + 8) * CHN + col) =
                make_float2(d[mt][nt][2] + b0, d[mt][nt][3] + b1);
        }
}

__global__ __launch_bounds__(256, 4) void k_codeU(const float* __restrict__ cb)
{
    __shared__ float As[32][68];
    __shared__ float Bs[32][68];
    int n0 = blockIdx.x * 64, j0 = blockIdx.y * 64;
    int t = j0 >> 8, o0 = j0 & 255;
    int tid = threadIdx.x, tx = tid & 15, ty = tid >> 4;

    float acc[4][4];
#pragma unroll
    for (int i = 0; i < 4; ++i)
#pragma unroll
        for (int j = 0; j < 4; ++j) acc[i][j] = 0.f;

#pragma unroll 1
    for (int k0 = 0; k0 < 256; k0 += 32) {
#pragma unroll
        for (int l = 0; l < 2; ++l) {
            int idx = tid + l * 256;
            int i = idx >> 3, kv = (idx & 7) << 2;
            float4 v = *(const float4*)(cb + (size_t)(n0 + i) * CHN + k0 + kv);
            As[kv + 0][i] = v.x; As[kv + 1][i] = v.y;
            As[kv + 2][i] = v.z; As[kv + 3][i] = v.w;
        }
#pragma unroll
        for (int l = 0; l < 2; ++l) {
            int idx = tid + l * 256;
            int k = idx >> 4, ov = (idx & 15) << 2;
            *(float4*)&Bs[k][ov] =
                *(const float4*)(g_wTu + ((size_t)(t * CHN) + k0 + k) * CHN + o0 + ov);
        }
        __syncthreads();
#pragma unroll
        for (int k = 0; k < 32; ++k) {
            float4 a4 = *(const float4*)&As[k][ty << 2];
            float4 b4 = *(const float4*)&Bs[k][tx << 2];
            float a[4] = {a4.x, a4.y, a4.z, a4.w};
            float b[4] = {b4.x, b4.y, b4.z, b4.w};
#pragma unroll
            for (int i = 0; i < 4; ++i)
#pragma unroll
                for (int j = 0; j < 4; ++j)
                    acc[i][j] = fmaf(a[i], b[j], acc[i][j]);
        }
        __syncthreads();
    }
    int j_base = j0 + (tx << 2), n_base = n0 + (ty << 2);
#pragma unroll
    for (int i = 0; i < 4; ++i)
        *(float4*)(g_U + (size_t)(n_base + i) * (9 * CHN) + j_base) =
            make_float4(acc[i][0], acc[i][1], acc[i][2], acc[i][3]);
}

// ---- pass 1: bf16 screening --------------------------------------------------
#define P1_STRIDE  272
#define P1_SM_B    (128 * P1_STRIDE)
#define P1_SM_CN   (2 * 128 * P1_STRIDE)
#define P1_SM_TOTAL (P1_SM_CN + 512)

__device__ __forceinline__ void p1_stage(char* dst, const float* __restrict__ src,
                                         int k0, int tid)
{
#pragma unroll
    for (int l = 0; l < 8; ++l) {
        int it = tid + l * 256;
        int row = it >> 4, kg = it & 15;
        const float4* s4 = (const float4*)(src + (size_t)row * CHN + k0 + kg * 8);
        float4 v0 = s4[0], v1 = s4[1];
        __nv_bfloat162 b0 = __floats2bfloat162_rn(v0.x, v0.y);
        __nv_bfloat162 b1 = __floats2bfloat162_rn(v0.z, v0.w);
        __nv_bfloat162 b2 = __floats2bfloat162_rn(v1.x, v1.y);
        __nv_bfloat162 b3 = __floats2bfloat162_rn(v1.z, v1.w);
        *(uint4*)(dst + row * P1_STRIDE + kg * 16) =
            make_uint4(*(uint32_t*)&b0, *(uint32_t*)&b1,
                       *(uint32_t*)&b2, *(uint32_t*)&b3);
    }
}

__global__ __launch_bounds__(256, 2) void k_pass1(const float* __restrict__ cb)
{
    extern __shared__ char sm[];
    uint32_t smb = smem_u32(sm);
    float* cns = (float*)(sm + P1_SM_CN);
    int tid = threadIdx.x, lane = tid & 31, wid = tid >> 5;
    int warp_m = wid >> 2, warp_n = wid & 3;
    int p0 = blockIdx.x * 128, j0 = blockIdx.y * 128;

    if (tid < 128) cns[tid] = g_cn[j0 + tid];

    float d[4][4][4];
#pragma unroll
    for (int mt = 0; mt < 4; ++mt)
#pragma unroll
        for (int nt = 0; nt < 4; ++nt)
#pragma unroll
            for (int r = 0; r < 4; ++r) d[mt][nt][r] = 0.f;

#pragma unroll 1
    for (int kk = 0; kk < 2; ++kk) {
        __syncthreads();
        p1_stage(sm, g_ze + (size_t)p0 * CHN, kk * 128, tid);
        p1_stage(sm + P1_SM_B, cb + (size_t)j0 * CHN, kk * 128, tid);
        __syncthreads();

        uint32_t a_base = smb + (uint32_t)(warp_m * 64 + (lane & 15)) * P1_STRIDE
                        + (uint32_t)(lane >> 4) * 16;
        uint32_t b_base = smb + P1_SM_B + (uint32_t)(warp_n * 32 + (lane & 7)) * P1_STRIDE
                        + (uint32_t)((lane >> 3) & 1) * 16;
#pragma unroll
        for (int ks = 0; ks < 8; ++ks) {
            uint32_t a[4][4], b[4][2];
#pragma unroll
            for (int mt = 0; mt < 4; ++mt) {
                uint32_t addr = a_base + (uint32_t)(mt * 16) * P1_STRIDE + ks * 32;
                asm volatile("ldmatrix.sync.aligned.m8n8.x4.shared.b16 {%0,%1,%2,%3}, [%4];"
                    : "=r"(a[mt][0]), "=r"(a[mt][1]), "=r"(a[mt][2]), "=r"(a[mt][3])
                    : "r"(addr));
            }
#pragma unroll
            for (int nt = 0; nt < 4; ++nt) {
                uint32_t addr = b_base + (uint32_t)(nt * 8) * P1_STRIDE + ks * 32;
                asm volatile("ldmatrix.sync.aligned.m8n8.x2.shared.b16 {%0,%1}, [%2];"
                    : "=r"(b[nt][0]), "=r"(b[nt][1]) : "r"(addr));
            }
#pragma unroll
            for (int mt = 0; mt < 4; ++mt)
#pragma unroll
                for (int nt = 0; nt < 4; ++nt)
                    asm volatile("mma.sync.aligned.m16n8k16.row.col.f32.bf16.bf16.f32 "
                        "{%0,%1,%2,%3}, {%4,%5,%6,%7}, {%8,%9}, {%0,%1,%2,%3};"
                        : "+f"(d[mt][nt][0]), "+f"(d[mt][nt][1]),
                          "+f"(d[mt][nt][2]), "+f"(d[mt][nt][3])
                        : "r"(a[mt][0]), "r"(a[mt][1]), "r"(a[mt][2]), "r"(a[mt][3]),
                          "r"(b[nt][0]), "r"(b[nt][1]));
        }
    }

    int r = lane >> 2, cp = (lane & 3) * 2;
#pragma unroll
    for (int mt = 0; mt < 4; ++mt)
#pragma unroll
        for (int nt = 0; nt < 4; ++nt) {
            int col = warp_n * 32 + nt * 8 + cp;
            float cn0 = cns[col], cn1 = cns[col + 1];
            int px0 = p0 + warp_m * 64 + mt * 16 + r;
            __half2 h0 = __floats2half2_rn(cn0 - 2.0f * d[mt][nt][0],
                                           cn1 - 2.0f * d[mt][nt][1]);
            __half2 h1 = __floats2half2_rn(cn0 - 2.0f * d[mt][nt][2],
                                           cn1 - 2.0f * d[mt][nt][3]);
            *(uint32_t*)(g_S + (size_t)px0 * NE + j0 + col) = *(uint32_t*)&h0;
            *(uint32_t*)(g_S + (size_t)(px0 + 8) * NE + j0 + col) = *(uint32_t*)&h1;
        }
}

// ---- pass 2: certify winner (gap >= THETA) or mark risky --------------------
__global__ __launch_bounds__(256) void k_argmin2(const float* __restrict__ cb)
{
    __shared__ int s_cand[8][64];
    __shared__ int s_cnt[8];
    int wid = threadIdx.x >> 5, lid = threadIdx.x & 31;
    int p = blockIdx.x * 8 + wid;

    const uint32_t* Srow = (const uint32_t*)(g_S + (size_t)p * NE);
    float v[32], m = 3.4e38f;
#pragma unroll
    for (int c = 0; c < 16; ++c) {
        uint32_t u = Srow[c * 32 + lid];
        float2 f = __half22float2(*(__half2*)&u);
        v[c * 2] = f.x; v[c * 2 + 1] = f.y;
        m = fminf(m, fminf(f.x, f.y));
    }
#pragma unroll
    for (int o = 16; o; o >>= 1) m = fminf(m, __shfl_xor_sync(0xffffffffu, m, o));
    float thr = m + MARGIN;

    if (lid == 0) s_cnt[wid] = 0;
    __syncwarp();
#pragma unroll
    for (int c = 0; c < 16; ++c) {
        if (v[c * 2] <= thr) {
            int pos = atomicAdd(&s_cnt[wid], 1);
            if (pos < 64) s_cand[wid][pos] = (c * 32 + lid) * 2;
        }
        if (v[c * 2 + 1] <= thr) {
            int pos = atomicAdd(&s_cnt[wid], 1);
            if (pos < 64) s_cand[wid][pos] = (c * 32 + lid) * 2 + 1;
        }
    }
    __syncwarp();
    int cntRaw = s_cnt[wid];
    int cnt = cntRaw > 64 ? 64 : cntRaw;

    float zn = g_zn[p];
    const float* zeR = g_ze + (size_t)p * CHN;
    float d1 = 3.4e38f, d2 = 3.4e38f;
    int j1 = 0;
#pragma unroll 1
    for (int base = 0; base < cnt; base += 32) {
        int slot = base + lid;
        float dd = 3.4e38f;
        int jj = 0;
        if (slot < cnt) {
            jj = s_cand[wid][slot];
            const float* cbR = cb + (size_t)jj * CHN;
            float dot = 0.f;
#pragma unroll 8
            for (int k = 0; k < CHN; ++k)
                dot = fmaf(zeR[k], cbR[k], dot);
            dd = __fadd_rn(__fadd_rn(zn, g_cn[jj]), -(2.0f * dot));
        }
        if (dd < d1) { d2 = d1; d1 = dd; j1 = jj; }
        else d2 = fminf(d2, dd);
    }
#pragma unroll
    for (int o = 16; o; o >>= 1) {
        float od1 = __shfl_xor_sync(0xffffffffu, d1, o);
        int   oj1 = __shfl_xor_sync(0xffffffffu, j1, o);
        float od2 = __shfl_xor_sync(0xffffffffu, d2, o);
        if (od1 < d1) { d2 = fminf(d1, od2); d1 = od1; j1 = oj1; }
        else d2 = fminf(d2, od1);
    }
    if (lid == 0) {
        if (cntRaw <= 64 && (d2 - d1) >= THETA) g_idx[p] = j1;
        else { int pos = atomicAdd(&g_nrisky, 1); g_risky[pos] = p; }
    }
}

// ---- fixup: exact reference chain for risky pixels (16 px per block) --------
__global__ __launch_bounds__(256) void k_fix(const float* __restrict__ cb,
                                             const float* __restrict__ emb_b)
{
    __shared__ float aS[16][CHN];
    __shared__ float zeS[16][CHN];
    __shared__ int sRow[16];
    __shared__ int sP[16];

    int tid = threadIdx.x;
    int pl = tid >> 4, og = tid & 15;
    int nr = g_nrisky;

    for (int base = blockIdx.x * 16; base < nr; base += gridDim.x * 16) {
        int np = nr - base; if (np > 16) np = 16;
        __syncthreads();
        if (tid < 16) sP[tid] = g_risky[base + ((tid < np) ? tid : 0)];
        float acc[16];
#pragma unroll
        for (int j = 0; j < 16; ++j) acc[j] = 0.f;
#pragma unroll 1
        for (int t = 0; t < 9; ++t) {
            int dy = t / 3 - 1, dx = t - (t / 3) * 3 - 1;
            __syncthreads();
            if (tid < 16) {
                int pp = sP[tid];
                int y = (pp >> 5) & 31, x = pp & 31;
                int yy = y + dy, xx = x + dx;
                sRow[tid] = ((unsigned)yy < 32u && (unsigned)xx < 32u)
                                ? (pp + dy * 32 + dx) : -1;
            }
            __syncthreads();
#pragma unroll
            for (int l = 0; l < 4; ++l) {
                int it = tid + l * 256;
                int r = it >> 6, cg = it & 63;
                int src = sRow[r];
                float4 vv = make_float4(0.f, 0.f, 0.f, 0.f);
                if (src >= 0) vv = *(const float4*)(g_zT + (size_t)src * CHN + cg * 4);
                *(float4*)&aS[r][cg * 4] = vv;
            }
            __syncthreads();
            if (sRow[pl] >= 0) {
#pragma unroll 4
                for (int c = 0; c < CHN; ++c) {
                    float a = aS[pl][c];
                    const float* w = g_wTe + ((size_t)(t * CHN) + c) * CHN + og * 16;
                    float4 w0 = *(const float4*)(w);
                    float4 w1 = *(const float4*)(w + 4);
                    float4 w2 = *(const float4*)(w + 8);
                    float4 w3 = *(const float4*)(w + 12);
                    acc[0] = fmaf(a, w0.x, acc[0]);  acc[1] = fmaf(a, w0.y, acc[1]);
                    acc[2] = fmaf(a, w0.z, acc[2]);  acc[3] = fmaf(a, w0.w, acc[3]);
                    acc[4] = fmaf(a, w1.x, acc[4]);  acc[5] = fmaf(a, w1.y, acc[5]);
                    acc[6] = fmaf(a, w1.z, acc[6]);  acc[7] = fmaf(a, w1.w, acc[7]);
                    acc[8] = fmaf(a, w2.x, acc[8]);  acc[9] = fmaf(a, w2.y, acc[9]);
                    acc[10] = fmaf(a, w2.z, acc[10]); acc[11] = fmaf(a, w2.w, acc[11]);
                    acc[12] = fmaf(a, w3.x, acc[12]); acc[13] = fmaf(a, w3.y, acc[13]);
                    acc[14] = fmaf(a, w3.z, acc[14]); acc[15] = fmaf(a, w3.w, acc[15]);
                }
            }
        }
        __syncthreads();
#pragma unroll
        for (int j = 0; j < 16; ++j)
            zeS[pl][og * 16 + j] = __fadd_rn(acc[j], emb_b[og * 16 + j]);
        __syncthreads();
        if (tid < np) {
            int pp = sP[tid];
            float zn = row_sumsq_seq(zeS[tid]);
            const __half* Sr = g_S + (size_t)pp * NE;
            float mv = 3.4e38f;
            for (int j = 0; j < NE; ++j) mv = fminf(mv, __half2float(Sr[j]));
            float thr2 = mv + MARGIN;
            float bd = 3.4e38f; int bj = 0;
            for (int j = 0; j < NE; ++j) {
                if (__half2float(Sr[j]) <= thr2) {
                    const float* cbR = cb + (size_t)j * CHN;
                    float dot = 0.f;
#pragma unroll 8
                    for (int c = 0; c < CHN; ++c)
                        dot = fmaf(zeS[tid][c], cbR[c], dot);
                    float dd = __fadd_rn(__fadd_rn(zn, g_cn[j]), -(2.0f * dot));
                    if (dd < bd) { bd = dd; bj = j; }
                }
            }
            g_idx[pp] = bj;
        }
    }
}

__global__ __launch_bounds__(256) void k_gather_loss(const float* __restrict__ cb,
                                                     float* __restrict__ out_idx)
{
    int warp = threadIdx.x >> 5, lane = threadIdx.x & 31;
    int p = blockIdx.x * 8 + warp;
    int code = g_idx[p];
    if (lane == 0) out_idx[p] = (float)code;
    const float4* src = (const float4*)(cb + (size_t)code * CHN);
    const float4* zes = (const float4*)(g_ze + (size_t)p * CHN);
    float s = 0.f;
#pragma unroll
    for (int v = lane; v < 64; v += 32) {
        float4 c = src[v], e = zes[v];
        float d0 = c.x - e.x, d1 = c.y - e.y, d2 = c.z - e.z, d3 = c.w - e.w;
        s += d0 * d0 + d1 * d1 + d2 * d2 + d3 * d3;
    }
#pragma unroll
    for (int o = 16; o; o >>= 1) s += __shfl_xor_sync(0xffffffffu, s, o);
    __shared__ float sm[8];
    if (lane == 0) sm[warp] = s;
    __syncthreads();
    if (threadIdx.x == 0) {
        float t = 0.f;
#pragma unroll
        for (int w = 0; w < 8; ++w) t += sm[w];
        g_partial[blockIdx.x] = t;
    }
}

__global__ void k_loss_final(float* __restrict__ out_loss)
{
    __shared__ float sm[32];
    int tid = threadIdx.x;
    float s = 0.f;
#pragma unroll
    for (int i = tid; i < 4096; i += 1024) s += g_partial[i];
#pragma unroll
    for (int o = 16; o; o >>= 1) s += __shfl_xor_sync(0xffffffffu, s, o);
    if ((tid & 31) == 0) sm[tid >> 5] = s;
    __syncthreads();
    if (tid < 32) {
        float v = sm[tid];
#pragma unroll
        for (int o = 16; o; o >>= 1) v += __shfl_xor_sync(0xffffffffu, v, o);
        if (tid == 0) out_loss[0] = v * (1.25f / 8388608.f);
    }
}

__global__ __launch_bounds__(256) void k_out_gather(const float* __restrict__ bias,
                                                    float* __restrict__ out)
{
    __shared__ float sm[32][257];
    __shared__ int sN[32][9];
    int p0 = blockIdx.x * 32;
    int tid = threadIdx.x;
    int px = tid >> 3, og = tid & 7;
    int y = (p0 >> 5) & 31;

    if (og == 0) {
#pragma unroll
        for (int t = 0; t < 9; ++t) {
            int dy = t / 3 - 1, dx = t - (t / 3) * 3 - 1;
            int yy = y + dy, xx = px + dx;
            sN[px][t] = ((unsigned)yy < 32u && (unsigned)xx < 32u)
                            ? g_idx[p0 + px + dy * 32 + dx] : -1;
        }
    }
    __syncthreads();

    float4 acc[8];
#pragma unroll
    for (int k = 0; k < 8; ++k) acc[k] = make_float4(0.f, 0.f, 0.f, 0.f);
#pragma unroll
    for (int t = 0; t < 9; ++t) {
        int n = sN[px][t];
        if (n >= 0) {
            const float4* u = (const float4*)(g_U + ((size_t)n * 9 + t) * CHN + og * 32);
#pragma unroll
            for (int k = 0; k < 8; ++k) {
                float4 v = u[k];
                acc[k].x = __fadd_rn(acc[k].x, v.x);
                acc[k].y = __fadd_rn(acc[k].y, v.y);
                acc[k].z = __fadd_rn(acc[k].z, v.z);
                acc[k].w = __fadd_rn(acc[k].w, v.w);
            }
        }
    }
    const float4* bb4 = (const float4*)(bias + og * 32);
#pragma unroll
    for (int k = 0; k < 8; ++k) {
        float4 b4 = bb4[k];
        int ob = og * 32 + k * 4;
        sm[px][ob + 0] = __fadd_rn(acc[k].x, b4.x);
        sm[px][ob + 1] = __fadd_rn(acc[k].y, b4.y);
        sm[px][ob + 2] = __fadd_rn(acc[k].z, b4.z);
        sm[px][ob + 3] = __fadd_rn(acc[k].w, b4.w);
    }
    __syncthreads();
    int b = p0 >> 10, hw0 = p0 & 1023;
    int warp = tid >> 5, lane = tid & 31;
#pragma unroll
    for (int oo = 0; oo < 32; ++oo) {
        int o = oo * 8 + warp;
        out[((size_t)(b * CHN + o)) * HW + hw0 + lane] = sm[lane][o];
    }
}

extern "C" void kernel_launch(void* const* d_in, const int* in_sizes, int n_in,
                              void* d_out, int out_size)
{
    const float* z       = (const float*)d_in[0];
    const float* emb_w   = (const float*)d_in[1];
    const float* emb_b   = (const float*)d_in[2];
    const float* cb      = (const float*)d_in[3];
    const float* unemb_w = (const float*)d_in[4];
    const float* unemb_b = (const float*)d_in[5];

    float* out      = (float*)d_out;
    float* out_loss = out + LOSS_OFF;
    float* out_idx  = out + IDX_OFF;

    cudaFuncSetAttribute(k_pass1, cudaFuncAttributeMaxDynamicSharedMemorySize,
                         P1_SM_TOTAL);
    cudaFuncSetAttribute(k_conv_bf16, cudaFuncAttributeMaxDynamicSharedMemorySize,
                         CM_TOTAL);

    k_transpose<<<dim3(32, 8, 32), dim3(32, 8)>>>(z);
    k_reorgW<<<2304, 256>>>(emb_w, 0);
    k_reorgW<<<2304, 256>>>(unemb_w, 1);
    k_code_norms<<<8, 128>>>(cb);
    k_codeU<<<dim3(16, 36), 256>>>(cb);

    // approx embed conv (single-term bf16 tensor-core), pass1-shaped
    k_conv_bf16<<<dim3(256, 2), 256, CM_TOTAL>>>(emb_b);
    k_row_norms<<<256, 128>>>();

    k_pass1<<<dim3(256, 8), 256, P1_SM_TOTAL>>>(cb);
    k_argmin2<<<4096, 256>>>(cb);
    k_fix<<<256, 256>>>(cb, emb_b);

    k_gather_loss<<<4096, 256>>>(cb, out_idx);
    k_loss_final<<<1, 1024>>>(out_loss);
    k_out_gather<<<1024, 256>>>(unemb_b, out);
}

// round 17
// speedup vs baseline: 2.4587x; 2.4587x over previous
#include <cuda_runtime.h>
#include <cuda_bf16.h>
#include <cuda_fp16.h>
#include <cstdint>

// Problem constants
#define BATCH   32
#define CHN     256      // in_c == e_dim == 256
#define HW      1024     // 32*32
#define P_TOTAL 32768    // B*H*W
#define NE      1024     // codebook entries

#define OUT_ELEMS   8388608   // 32*256*32*32
#define LOSS_OFF    8388608
#define IDX_OFF     8388609

#define MARGIN  4e-3f

// ---------------- scratch (device globals; no allocation allowed) ----------
__device__ float  g_zT[P_TOTAL * CHN];    // z in NHWC  [p][c]
__device__ float  g_ze[P_TOTAL * CHN];    // embedded   [p][e]
__device__ float  g_wTe[9 * CHN * CHN];   // emb  weights [t][i][o]
__device__ float  g_wTu[9 * CHN * CHN];   // unemb weights [t][i][o]
__device__ float  g_U[NE * 9 * CHN];      // U[n][t][o]
__device__ float  g_cn[NE];               // ||e||^2 per code (ref rounding)
__device__ float  g_zn[P_TOTAL];          // ||ze||^2 per pixel (ref rounding)
__device__ __half g_S[(size_t)P_TOTAL * NE]; // approx scores cn-2dot (fp16)
__device__ int    g_idx[P_TOTAL];         // argmin indices
__device__ float  g_partial[4096];        // per-block loss partials

__device__ __forceinline__ uint32_t smem_u32(const void* p) {
    uint32_t a;
    asm("{ .reg .u64 t; cvta.to.shared.u64 t, %1; cvt.u32.u64 %0, t; }"
        : "=r"(a) : "l"(p));
    return a;
}

// ---------------- packed f32x2 helpers (each half = IEEE rn fp32, bitwise
// identical to scalar fmaf chains) ------------------------------------------
__device__ __forceinline__ uint64_t pk2(float lo, float hi) {
    uint64_t r;
    asm("mov.b64 %0, {%1, %2};" : "=l"(r) : "f"(lo), "f"(hi));
    return r;
}
__device__ __forceinline__ void unpk2(uint64_t v, float& lo, float& hi) {
    asm("mov.b64 {%0, %1}, %2;" : "=f"(lo), "=f"(hi) : "l"(v));
}
__device__ __forceinline__ uint64_t ffma2(uint64_t a, uint64_t b, uint64_t c) {
    uint64_t d;
    asm("fma.rn.f32x2 %0, %1, %2, %3;" : "=l"(d) : "l"(a), "l"(b), "l"(c));
    return d;
}

// ---------------- NCHW -> NHWC transpose of z ------------------------------
__global__ void k_transpose(const float* __restrict__ z)
{
    __shared__ float t[32][33];
    int b   = blockIdx.z;
    int c0  = blockIdx.y * 32;
    int hw0 = blockIdx.x * 32;
    int tx = threadIdx.x, ty = threadIdx.y;   // 32 x 8
#pragma unroll
    for (int r = 0; r < 32; r += 8)
        t[ty + r][tx] = z[((size_t)(b * CHN + c0 + ty + r)) * HW + hw0 + tx];
    __syncthreads();
#pragma unroll
    for (int r = 0; r < 32; r += 8)
        g_zT[((size_t)(b * HW + hw0 + ty + r)) * CHN + c0 + tx] = t[tx][ty + r];
}

// ---------------- weight reorg: w[o][i][t] -> wT[t][i][o] -------------------
__global__ void k_reorgW(const float* __restrict__ w, int which)
{
    int idx = blockIdx.x * 256 + threadIdx.x;
    if (idx >= 9 * CHN * CHN) return;
    int t = idx % 9;
    int i = (idx / 9) % CHN;
    int o = idx / (9 * CHN);
    float* dst = which ? g_wTu : g_wTe;
    dst[(t * CHN + i) * CHN + o] = w[idx];
}

// ---------------- strict-sequential sum of squares (ref replica) ------------
__device__ __forceinline__ float row_sumsq_seq(const float* __restrict__ row)
{
    float acc = 0.f;
#pragma unroll 8
    for (int c = 0; c < CHN; ++c)
        acc = __fadd_rn(acc, __fmul_rn(row[c], row[c]));
    return acc;
}

__global__ void k_code_norms(const float* __restrict__ cb)
{
    int code = blockIdx.x * 16 + threadIdx.x;   // 64 blocks x 16 -> spread SMs
    if (code >= NE) return;
    g_cn[code] = row_sumsq_seq(cb + (size_t)code * CHN);
}

__global__ void k_row_norms()
{
    int p = blockIdx.x * 128 + threadIdx.x;
    if (p >= P_TOTAL) return;
    g_zn[p] = row_sumsq_seq(g_ze + (size_t)p * CHN);
}

// ---------------- embed 3x3 SAME conv, f32x2 implicit GEMM -------------------
// Tile 128 px x 128 och, 256 threads, 8x8 per thread. Accumulators are f32x2
// pairs over adjacent pixels; each half's (tap, k) chain is bitwise identical
// to the scalar reference chain.
#define CV_STRIDE 132   // floats per smem row (128 + 4 pad, 16B-aligned rows)

__global__ __launch_bounds__(256, 2) void k_conv_embed(const float* __restrict__ bias)
{
    __shared__ float As[32][CV_STRIDE];   // [k][px]
    __shared__ float Bs[32][CV_STRIDE];   // [k][och]
    __shared__ int srcRow[128];

    int p0 = blockIdx.x * 128;
    int o0 = blockIdx.y * 128;
    int tid = threadIdx.x;
    int tx = tid & 15, ty = tid >> 4;     // tx: o-group, ty: px-group

    uint64_t acc[4][8];                   // [px-pair q][och j]
#pragma unroll
    for (int q = 0; q < 4; ++q)
#pragma unroll
        for (int j = 0; j < 8; ++j) acc[q][j] = 0ull;

#pragma unroll 1
    for (int t = 0; t < 9; ++t) {
        int dy = t / 3 - 1;
        int dx = t - (t / 3) * 3 - 1;
        if (tid < 128) {
            int p = p0 + tid;
            int y = (p >> 5) & 31, x = p & 31;
            int yy = y + dy, xx = x + dx;
            srcRow[tid] = ((unsigned)yy < 32u && (unsigned)xx < 32u)
                              ? (p + dy * 32 + dx) : -1;
        }
        __syncthreads();
#pragma unroll 1
        for (int k0 = 0; k0 < 256; k0 += 32) {
            // stage A: 128 px x 32 k (scatter k-major)
#pragma unroll
            for (int l = 0; l < 4; ++l) {
                int idx = tid + l * 256;      // 0..1023
                int px = idx & 127;
                int kc = idx >> 7;            // 0..7
                int row = srcRow[px];
                float4 v = make_float4(0.f, 0.f, 0.f, 0.f);
                if (row >= 0)
                    v = *(const float4*)(g_zT + (size_t)row * CHN + k0 + kc * 4);
                As[kc * 4 + 0][px] = v.x;
                As[kc * 4 + 1][px] = v.y;
                As[kc * 4 + 2][px] = v.z;
                As[kc * 4 + 3][px] = v.w;
            }
            // stage B: 32 k x 128 o (direct float4)
#pragma unroll
            for (int l = 0; l < 4; ++l) {
                int idx = tid + l * 256;
                int k  = idx >> 5;            // 0..31
                int oc = idx & 31;            // 0..31 (x4 floats)
                *(float4*)&Bs[k][oc * 4] =
                    *(const float4*)(g_wTe + ((size_t)(t * CHN) + k0 + k) * CHN
                                     + o0 + oc * 4);
            }
            __syncthreads();
#pragma unroll 4
            for (int k = 0; k < 32; ++k) {
                ulonglong2 a01 = *(const ulonglong2*)&As[k][ty * 8];
                ulonglong2 a23 = *(const ulonglong2*)&As[k][ty * 8 + 4];
                uint64_t ap[4] = {a01.x, a01.y, a23.x, a23.y};
                float4 b0 = *(const float4*)&Bs[k][tx * 8];
                float4 b1 = *(const float4*)&Bs[k][tx * 8 + 4];
                uint64_t bs[8] = {pk2(b0.x, b0.x), pk2(b0.y, b0.y),
                                  pk2(b0.z, b0.z), pk2(b0.w, b0.w),
                                  pk2(b1.x, b1.x), pk2(b1.y, b1.y),
                                  pk2(b1.z, b1.z), pk2(b1.w, b1.w)};
#pragma unroll
                for (int q = 0; q < 4; ++q)
#pragma unroll
                    for (int j = 0; j < 8; ++j)
                        acc[q][j] = ffma2(ap[q], bs[j], acc[q][j]);
            }
            __syncthreads();
        }
    }

    int o_base = o0 + tx * 8;
    int p_base = p0 + ty * 8;
    float bb[8];
#pragma unroll
    for (int j = 0; j < 8; ++j) bb[j] = bias[o_base + j];

#pragma unroll
    for (int q = 0; q < 4; ++q) {
        float lo[8], hi[8];
#pragma unroll
        for (int j = 0; j < 8; ++j) unpk2(acc[q][j], lo[j], hi[j]);
        float* r0 = g_ze + (size_t)(p_base + q * 2 + 0) * CHN + o_base;
        float* r1 = g_ze + (size_t)(p_base + q * 2 + 1) * CHN + o_base;
        *(float4*)(r0)     = make_float4(__fadd_rn(lo[0], bb[0]), __fadd_rn(lo[1], bb[1]),
                                         __fadd_rn(lo[2], bb[2]), __fadd_rn(lo[3], bb[3]));
        *(float4*)(r0 + 4) = make_float4(__fadd_rn(lo[4], bb[4]), __fadd_rn(lo[5], bb[5]),
                                         __fadd_rn(lo[6], bb[6]), __fadd_rn(lo[7], bb[7]));
        *(float4*)(r1)     = make_float4(__fadd_rn(hi[0], bb[0]), __fadd_rn(hi[1], bb[1]),
                                         __fadd_rn(hi[2], bb[2]), __fadd_rn(hi[3], bb[3]));
        *(float4*)(r1 + 4) = make_float4(__fadd_rn(hi[4], bb[4]), __fadd_rn(hi[5], bb[5]),
                                         __fadd_rn(hi[6], bb[6]), __fadd_rn(hi[7], bb[7]));
    }
}

// ---------------- code->tap table GEMM: U[n][t][o] --------------------------
__global__ __launch_bounds__(256, 4) void k_codeU(const float* __restrict__ cb)
{
    __shared__ float As[32][68];
    __shared__ float Bs[32][68];

    int n0 = blockIdx.x * 64;
    int j0 = blockIdx.y * 64;
    int t  = j0 >> 8;
    int o0 = j0 & 255;
    int tid = threadIdx.x;
    int tx = tid & 15, ty = tid >> 4;

    float acc[4][4];
#pragma unroll
    for (int i = 0; i < 4; ++i)
#pragma unroll
        for (int j = 0; j < 4; ++j) acc[i][j] = 0.f;

#pragma unroll 1
    for (int k0 = 0; k0 < 256; k0 += 32) {
#pragma unroll
        for (int l = 0; l < 2; ++l) {
            int idx = tid + l * 256;
            int i  = idx >> 3;
            int kv = (idx & 7) << 2;
            float4 v = *(const float4*)(cb + (size_t)(n0 + i) * CHN + k0 + kv);
            As[kv + 0][i] = v.x; As[kv + 1][i] = v.y;
            As[kv + 2][i] = v.z; As[kv + 3][i] = v.w;
        }
#pragma unroll
        for (int l = 0; l < 2; ++l) {
            int idx = tid + l * 256;
            int k  = idx >> 4;
            int ov = (idx & 15) << 2;
            *(float4*)&Bs[k][ov] =
                *(const float4*)(g_wTu + ((size_t)(t * CHN) + k0 + k) * CHN + o0 + ov);
        }
        __syncthreads();
#pragma unroll
        for (int k = 0; k < 32; ++k) {
            float4 a4 = *(const float4*)&As[k][ty << 2];
            float4 b4 = *(const float4*)&Bs[k][tx << 2];
            float a[4] = {a4.x, a4.y, a4.z, a4.w};
            float b[4] = {b4.x, b4.y, b4.z, b4.w};
#pragma unroll
            for (int i = 0; i < 4; ++i)
#pragma unroll
                for (int j = 0; j < 4; ++j)
                    acc[i][j] = fmaf(a[i], b[j], acc[i][j]);
        }
        __syncthreads();
    }

    int j_base = j0 + (tx << 2);
    int n_base = n0 + (ty << 2);
#pragma unroll
    for (int i = 0; i < 4; ++i)
        *(float4*)(g_U + (size_t)(n_base + i) * (9 * CHN) + j_base) =
            make_float4(acc[i][0], acc[i][1], acc[i][2], acc[i][3]);
}

// ---------------- PASS 1: bf16 mma.sync screening GEMM -----------------------
#define P1_STRIDE  272
#define P1_SM_A    0
#define P1_SM_B    (128 * P1_STRIDE)
#define P1_SM_CN   (2 * 128 * P1_STRIDE)
#define P1_SM_TOTAL (P1_SM_CN + 512)

__device__ __forceinline__ void p1_stage(char* dst, const float* __restrict__ src,
                                         int k0, int tid)
{
#pragma unroll
    for (int l = 0; l < 8; ++l) {
        int it = tid + l * 256;
        int row = it >> 4;
        int kg  = it & 15;
        const float4* s4 = (const float4*)(src + (size_t)row * CHN + k0 + kg * 8);
        float4 v0 = s4[0], v1 = s4[1];
        __nv_bfloat162 b0 = __floats2bfloat162_rn(v0.x, v0.y);
        __nv_bfloat162 b1 = __floats2bfloat162_rn(v0.z, v0.w);
        __nv_bfloat162 b2 = __floats2bfloat162_rn(v1.x, v1.y);
        __nv_bfloat162 b3 = __floats2bfloat162_rn(v1.z, v1.w);
        *(uint4*)(dst + row * P1_STRIDE + kg * 16) =
            make_uint4(*(uint32_t*)&b0, *(uint32_t*)&b1,
                       *(uint32_t*)&b2, *(uint32_t*)&b3);
    }
}

__global__ __launch_bounds__(256, 2) void k_pass1(const float* __restrict__ cb)
{
    extern __shared__ char sm[];
    uint32_t smb = smem_u32(sm);
    float* cns = (float*)(sm + P1_SM_CN);

    int tid = threadIdx.x;
    int lane = tid & 31, wid = tid >> 5;
    int warp_m = wid >> 2, warp_n = wid & 3;
    int p0 = blockIdx.x * 128, j0 = blockIdx.y * 128;

    if (tid < 128) cns[tid] = g_cn[j0 + tid];

    float d[4][4][4];
#pragma unroll
    for (int mt = 0; mt < 4; ++mt)
#pragma unroll
        for (int nt = 0; nt < 4; ++nt)
#pragma unroll
            for (int r = 0; r < 4; ++r) d[mt][nt][r] = 0.f;

#pragma unroll 1
    for (int kk = 0; kk < 2; ++kk) {
        __syncthreads();
        p1_stage(sm + P1_SM_A, g_ze + (size_t)p0 * CHN, kk * 128, tid);
        p1_stage(sm + P1_SM_B, cb + (size_t)j0 * CHN, kk * 128, tid);
        __syncthreads();

        uint32_t a_base = smb + P1_SM_A
                        + (uint32_t)(warp_m * 64 + (lane & 15)) * P1_STRIDE
                        + (uint32_t)(lane >> 4) * 16;
        uint32_t b_base = smb + P1_SM_B
                        + (uint32_t)(warp_n * 32 + (lane & 7)) * P1_STRIDE
                        + (uint32_t)((lane >> 3) & 1) * 16;

#pragma unroll
        for (int ks = 0; ks < 8; ++ks) {
            uint32_t a[4][4];
#pragma unroll
            for (int mt = 0; mt < 4; ++mt) {
                uint32_t addr = a_base + (uint32_t)(mt * 16) * P1_STRIDE + ks * 32;
                asm volatile(
                    "ldmatrix.sync.aligned.m8n8.x4.shared.b16 {%0,%1,%2,%3}, [%4];"
                    : "=r"(a[mt][0]), "=r"(a[mt][1]), "=r"(a[mt][2]), "=r"(a[mt][3])
                    : "r"(addr));
            }
            uint32_t b[4][2];
#pragma unroll
            for (int nt = 0; nt < 4; ++nt) {
                uint32_t addr = b_base + (uint32_t)(nt * 8) * P1_STRIDE + ks * 32;
                asm volatile(
                    "ldmatrix.sync.aligned.m8n8.x2.shared.b16 {%0,%1}, [%2];"
                    : "=r"(b[nt][0]), "=r"(b[nt][1]) : "r"(addr));
            }
#pragma unroll
            for (int mt = 0; mt < 4; ++mt)
#pragma unroll
                for (int nt = 0; nt < 4; ++nt)
                    asm volatile(
                        "mma.sync.aligned.m16n8k16.row.col.f32.bf16.bf16.f32 "
                        "{%0,%1,%2,%3}, {%4,%5,%6,%7}, {%8,%9}, {%0,%1,%2,%3};"
                        : "+f"(d[mt][nt][0]), "+f"(d[mt][nt][1]),
                          "+f"(d[mt][nt][2]), "+f"(d[mt][nt][3])
                        : "r"(a[mt][0]), "r"(a[mt][1]), "r"(a[mt][2]), "r"(a[mt][3]),
                          "r"(b[nt][0]), "r"(b[nt][1]));
        }
    }

    int r = lane >> 2, cp = (lane & 3) * 2;
#pragma unroll
    for (int mt = 0; mt < 4; ++mt) {
#pragma unroll
        for (int nt = 0; nt < 4; ++nt) {
            int col = warp_n * 32 + nt * 8 + cp;
            float cn0 = cns[col], cn1 = cns[col + 1];
            int px0 = p0 + warp_m * 64 + mt * 16 + r;
            __half2 h0 = __floats2half2_rn(cn0 - 2.0f * d[mt][nt][0],
                                           cn1 - 2.0f * d[mt][nt][1]);
            __half2 h1 = __floats2half2_rn(cn0 - 2.0f * d[mt][nt][2],
                                           cn1 - 2.0f * d[mt][nt][3]);
            *(uint32_t*)(g_S + (size_t)px0 * NE + j0 + col) = *(uint32_t*)&h0;
            *(uint32_t*)(g_S + (size_t)(px0 + 8) * NE + j0 + col) = *(uint32_t*)&h1;
        }
    }
}

// ---------------- PASS 2: candidate verification + exact argmin --------------
__global__ __launch_bounds__(256) void k_argmin2(const float* __restrict__ cb)
{
    __shared__ int s_cand[8][64];
    __shared__ int s_cnt[8];

    int wid = threadIdx.x >> 5, lid = threadIdx.x & 31;
    int p = blockIdx.x * 8 + wid;

    const uint32_t* Srow = (const uint32_t*)(g_S + (size_t)p * NE);
    float v[32];
    float m = 3.4e38f;
#pragma unroll
    for (int c = 0; c < 16; ++c) {
        uint32_t u = Srow[c * 32 + lid];
        __half2 h2 = *(__half2*)&u;
        float2 f = __half22float2(h2);
        v[c * 2 + 0] = f.x;
        v[c * 2 + 1] = f.y;
        m = fminf(m, fminf(f.x, f.y));
    }
#pragma unroll
    for (int o = 16; o; o >>= 1) m = fminf(m, __shfl_xor_sync(0xffffffffu, m, o));
    float thr = m + MARGIN;

    if (lid == 0) s_cnt[wid] = 0;
    __syncwarp();
#pragma unroll
    for (int c = 0; c < 16; ++c) {
        if (v[c * 2 + 0] <= thr) {
            int pos = atomicAdd(&s_cnt[wid], 1);
            if (pos < 64) s_cand[wid][pos] = (c * 32 + lid) * 2;
        }
        if (v[c * 2 + 1] <= thr) {
            int pos = atomicAdd(&s_cnt[wid], 1);
            if (pos < 64) s_cand[wid][pos] = (c * 32 + lid) * 2 + 1;
        }
    }
    __syncwarp();
    int cnt = s_cnt[wid];
    if (cnt > 64) cnt = 64;

    float zn = g_zn[p];
    const float* zeR = g_ze + (size_t)p * CHN;

    float bestd = 3.4e38f;
    int   bestj = 0x7fffffff;
#pragma unroll 1
    for (int base = 0; base < cnt; base += 32) {
        int slot = base + lid;
        float d = 3.4e38f;
        int   j = 0x7fffffff;
        if (slot < cnt) {
            j = s_cand[wid][slot];
            const float* cbR = cb + (size_t)j * CHN;
            float dot = 0.f;
#pragma unroll 8
            for (int k = 0; k < CHN; ++k)
                dot = fmaf(zeR[k], cbR[k], dot);
            d = __fadd_rn(__fadd_rn(zn, g_cn[j]), -(2.0f * dot));
        }
        if (d < bestd || (d == bestd && j < bestj)) { bestd = d; bestj = j; }
    }
#pragma unroll
    for (int o = 16; o; o >>= 1) {
        float od = __shfl_xor_sync(0xffffffffu, bestd, o);
        int   oj = __shfl_xor_sync(0xffffffffu, bestj, o);
        if (od < bestd || (od == bestd && oj < bestj)) { bestd = od; bestj = oj; }
    }
    if (lid == 0) g_idx[p] = bestj;
}

// ---------------- idx output + partial loss sums -----------------------------
__global__ __launch_bounds__(256) void k_gather_loss(const float* __restrict__ cb,
                                                     float* __restrict__ out_idx)
{
    int warp = threadIdx.x >> 5, lane = threadIdx.x & 31;
    int p = blockIdx.x * 8 + warp;
    int code = g_idx[p];
    if (lane == 0) out_idx[p] = (float)code;
    const float4* src = (const float4*)(cb + (size_t)code * CHN);
    const float4* zes = (const float4*)(g_ze + (size_t)p * CHN);
    float s = 0.f;
#pragma unroll
    for (int v = lane; v < 64; v += 32) {
        float4 c = src[v], e = zes[v];
        float d0 = c.x - e.x, d1 = c.y - e.y, d2 = c.z - e.z, d3 = c.w - e.w;
        s += d0 * d0 + d1 * d1 + d2 * d2 + d3 * d3;
    }
#pragma unroll
    for (int o = 16; o; o >>= 1) s += __shfl_xor_sync(0xffffffffu, s, o);
    __shared__ float sm[8];
    if (lane == 0) sm[warp] = s;
    __syncthreads();
    if (threadIdx.x == 0) {
        float t = 0.f;
#pragma unroll
        for (int w = 0; w < 8; ++w) t += sm[w];
        g_partial[blockIdx.x] = t;
    }
}

__global__ void k_loss_final(float* __restrict__ out_loss)
{
    __shared__ float sm[32];
    int tid = threadIdx.x;
    float s = 0.f;
#pragma unroll
    for (int i = tid; i < 4096; i += 1024) s += g_partial[i];
#pragma unroll
    for (int o = 16; o; o >>= 1) s += __shfl_xor_sync(0xffffffffu, s, o);
    if ((tid & 31) == 0) sm[tid >> 5] = s;
    __syncthreads();
    if (tid < 32) {
        float v = sm[tid];
#pragma unroll
        for (int o = 16; o; o >>= 1) v += __shfl_xor_sync(0xffffffffu, v, o);
        if (tid == 0) out_loss[0] = v * (1.25f / 8388608.f);
    }
}

// ---------------- unembed conv via U-table gather-sum ------------------------
__global__ __launch_bounds__(256) void k_out_gather(const float* __restrict__ bias,
                                                    float* __restrict__ out)
{
    __shared__ float sm[32][257];
    __shared__ int   sN[32][9];

    int p0 = blockIdx.x * 32;
    int tid = threadIdx.x;
    int px = tid >> 3, og = tid & 7;
    int y = (p0 >> 5) & 31;

    if (og == 0) {
#pragma unroll
        for (int t = 0; t < 9; ++t) {
            int dy = t / 3 - 1, dx = t - (t / 3) * 3 - 1;
            int yy = y + dy, xx = px + dx;
            sN[px][t] = ((unsigned)yy < 32u && (unsigned)xx < 32u)
                            ? g_idx[p0 + px + dy * 32 + dx] : -1;
        }
    }
    __syncthreads();

    float4 acc[8];
#pragma unroll
    for (int k = 0; k < 8; ++k) acc[k] = make_float4(0.f, 0.f, 0.f, 0.f);

#pragma unroll
    for (int t = 0; t < 9; ++t) {
        int n = sN[px][t];
        if (n >= 0) {
            const float4* u = (const float4*)(g_U + ((size_t)n * 9 + t) * CHN + og * 32);
#pragma unroll
            for (int k = 0; k < 8; ++k) {
                float4 v = u[k];
                acc[k].x = __fadd_rn(acc[k].x, v.x);
                acc[k].y = __fadd_rn(acc[k].y, v.y);
                acc[k].z = __fadd_rn(acc[k].z, v.z);
                acc[k].w = __fadd_rn(acc[k].w, v.w);
            }
        }
    }

    const float4* bb4 = (const float4*)(bias + og * 32);
#pragma unroll
    for (int k = 0; k < 8; ++k) {
        float4 b4 = bb4[k];
        int ob = og * 32 + k * 4;
        sm[px][ob + 0] = __fadd_rn(acc[k].x, b4.x);
        sm[px][ob + 1] = __fadd_rn(acc[k].y, b4.y);
        sm[px][ob + 2] = __fadd_rn(acc[k].z, b4.z);
        sm[px][ob + 3] = __fadd_rn(acc[k].w, b4.w);
    }
    __syncthreads();

    int b = p0 >> 10, hw0 = p0 & 1023;
    int warp = tid >> 5, lane = tid & 31;
#pragma unroll
    for (int oo = 0; oo < 32; ++oo) {
        int o = oo * 8 + warp;
        out[((size_t)(b * CHN + o)) * HW + hw0 + lane] = sm[lane][o];
    }
}

// ---------------- launch ----------------------------------------------------
extern "C" void kernel_launch(void* const* d_in, const int* in_sizes, int n_in,
                              void* d_out, int out_size)
{
    const float* z       = (const float*)d_in[0];
    const float* emb_w   = (const float*)d_in[1];
    const float* emb_b   = (const float*)d_in[2];
    const float* cb      = (const float*)d_in[3];
    const float* unemb_w = (const float*)d_in[4];
    const float* unemb_b = (const float*)d_in[5];

    float* out      = (float*)d_out;
    float* out_loss = out + LOSS_OFF;
    float* out_idx  = out + IDX_OFF;

    cudaFuncSetAttribute(k_pass1, cudaFuncAttributeMaxDynamicSharedMemorySize,
                         P1_SM_TOTAL);

    // prep
    k_transpose<<<dim3(32, 8, 32), dim3(32, 8)>>>(z);
    k_reorgW<<<2304, 256>>>(emb_w, 0);
    k_reorgW<<<2304, 256>>>(unemb_w, 1);
    k_code_norms<<<64, 16>>>(cb);

    // code->tap table for the unembed conv
    k_codeU<<<dim3(16, 36), 256>>>(cb);

    // embed conv -> g_ze (NHWC)  [bitwise ref-replica, f32x2]
    k_conv_embed<<<dim3(256, 2), 256>>>(emb_b);

    // per-pixel norms (reference-rounded)
    k_row_norms<<<256, 128>>>();

    // pass 1: bf16 tensor-core screening scores (mma.sync, base ISA)
    k_pass1<<<dim3(256, 8), 256, P1_SM_TOTAL>>>(cb);

    // pass 2: exact verification of candidates -> g_idx
    k_argmin2<<<4096, 256>>>(cb);

    // idx output + loss partials
    k_gather_loss<<<4096, 256>>>(cb, out_idx);
    k_loss_final<<<1, 1024>>>(out_loss);

    // unembed conv as table gather-sum -> d_out (NCHW)
    k_out_gather<<<1024, 256>>>(unemb_b, out);
}